// round 7
// baseline (speedup 1.0000x reference)
#include <cuda_runtime.h>
#include <math.h>
#include <cstdint>

// Problem constants
#define Bsz 2
#define SQd 256
#define SKd 512
#define Ed  512
#define Hd  256

#define NQ (Bsz*SQd)   // 512
#define NK (Bsz*SKd)   // 1024
#define OFF_QF 0
#define OFF_KF (OFF_QF + NQ*Hd)
#define OFF_QP (OFF_KF + NK*Hd)
#define OFF_KP (OFF_QP + NQ*Hd)
#define OFF_QV (OFF_KP + NK*Hd)
#define OFF_KV (OFF_QV + NQ*Hd)
#define SCRATCH_FLOATS (OFF_KV + NK*Hd)

__device__ float g_scratch[SCRATCH_FLOATS];
// int8 2-digit weights: [layer][digit][n][k], 256x256 each
__device__ __align__(16) signed char g_wq[4 * 65536];
// per-output-col scales (rowmax/127): [layer][n]
__device__ float g_wscale[2 * 256];

__device__ __forceinline__ float frelu(float x) { return x > 0.f ? x : 0.f; }
__device__ __forceinline__ float4 ldg4(const float* p) { return __ldg((const float4*)p); }

__device__ __forceinline__ uint32_t smem_to_u32(const void* p) {
    uint32_t a;
    asm("{ .reg .u64 t; cvta.to.shared.u64 t, %1; cvt.u32.u64 %0, t; }" : "=r"(a) : "l"(p));
    return a;
}
__device__ __forceinline__ void cp16(uint32_t dst, const void* src) {
    asm volatile("cp.async.cg.shared.global [%0], [%1], 16;" :: "r"(dst), "l"(src));
}
#define CP_COMMIT() asm volatile("cp.async.commit_group;" ::: "memory")
#define CP_WAIT0()  asm volatile("cp.async.wait_group 0;" ::: "memory")

// int8 mma m16n8k32 -> s32, accumulate in place
__device__ __forceinline__ void mma_s8(int* c, const uint32_t* a, const uint32_t* b) {
    asm volatile(
        "mma.sync.aligned.m16n8k32.row.col.s32.s8.s8.s32 "
        "{%0,%1,%2,%3}, {%4,%5,%6,%7}, {%8,%9}, {%0,%1,%2,%3};"
        : "+r"(c[0]), "+r"(c[1]), "+r"(c[2]), "+r"(c[3])
        : "r"(a[0]), "r"(a[1]), "r"(a[2]), "r"(a[3]), "r"(b[0]), "r"(b[1]));
}
__device__ __forceinline__ void ldsm4(uint32_t* r, uint32_t addr) {
    asm volatile("ldmatrix.sync.aligned.m8n8.x4.shared.b16 {%0,%1,%2,%3}, [%4];"
                 : "=r"(r[0]), "=r"(r[1]), "=r"(r[2]), "=r"(r[3]) : "r"(addr));
}
__device__ __forceinline__ int pack4(int x0, int x1, int x2, int x3) {
    return (x0 & 0xff) | ((x1 & 0xff) << 8) | ((x2 & 0xff) << 16) | ((x3 & 0xff) << 24);
}

#define INV254 (1.0f / 254.0f)

// ---------------------------------------------------------------------------
// Prep GEMM tile (verified since R2)
// ---------------------------------------------------------------------------
__device__ void gemm_tile(const float* __restrict__ A,
                          const float* __restrict__ W,
                          const float* __restrict__ bias,
                          float* __restrict__ C,
                          int K, int act, int row0, int col0)
{
    __shared__ float As[32 * 32];
    __shared__ float Ws[32 * 64];
    const int tid = threadIdx.x;
    const int tr  = tid >> 4;
    const int tc  = tid & 15;

    float acc0x=0.f,acc0y=0.f,acc0z=0.f,acc0w=0.f,acc1x=0.f,acc1y=0.f,acc1z=0.f,acc1w=0.f;
    if (bias) {
        float4 bb = ldg4(bias + col0 + tc * 4);
        acc0x=bb.x;acc0y=bb.y;acc0z=bb.z;acc0w=bb.w;
        acc1x=bb.x;acc1y=bb.y;acc1z=bb.z;acc1w=bb.w;
    }
    for (int kc = 0; kc < K; kc += 32) {
        __syncthreads();
        {   int r = tid >> 3; int ck = (tid & 7) * 4;
            *(float4*)(As + r * 32 + ck) = ldg4(A + (size_t)(row0 + r) * K + kc + ck); }
        {
            #pragma unroll
            for (int i = 0; i < 2; i++) {
                int f = tid + 256 * i; int k = f >> 4; int c = (f & 15) * 4;
                *(float4*)(Ws + k * 64 + c) = ldg4(W + (size_t)(kc + k) * 256 + col0 + c);
            } }
        __syncthreads();
        #pragma unroll 8
        for (int k = 0; k < 32; k++) {
            float a0 = As[(tr * 2) * 32 + k];
            float a1 = As[(tr * 2 + 1) * 32 + k];
            float4 w = *(float4*)(Ws + k * 64 + tc * 4);
            acc0x = fmaf(a0, w.x, acc0x); acc0y = fmaf(a0, w.y, acc0y);
            acc0z = fmaf(a0, w.z, acc0z); acc0w = fmaf(a0, w.w, acc0w);
            acc1x = fmaf(a1, w.x, acc1x); acc1y = fmaf(a1, w.y, acc1y);
            acc1z = fmaf(a1, w.z, acc1z); acc1w = fmaf(a1, w.w, acc1w);
        }
    }
    if (act) {
        acc0x=frelu(acc0x);acc0y=frelu(acc0y);acc0z=frelu(acc0z);acc0w=frelu(acc0w);
        acc1x=frelu(acc1x);acc1y=frelu(acc1y);acc1z=frelu(acc1z);acc1w=frelu(acc1w);
    }
    *(float4*)(C + (size_t)(row0+tr*2)  *256 + col0 + tc*4) = make_float4(acc0x,acc0y,acc0z,acc0w);
    *(float4*)(C + (size_t)(row0+tr*2+1)*256 + col0 + tc*4) = make_float4(acc1x,acc1y,acc1z,acc1w);
}

// Launch 1: both encoders. grid (4, 48)
__global__ void encoder_kernel(const float* __restrict__ query,
                               const float* __restrict__ key_,
                               const float* __restrict__ Wqe, const float* __restrict__ bqe,
                               const float* __restrict__ Wke, const float* __restrict__ bke)
{
    float* S = g_scratch;
    int y = blockIdx.y;
    if (y < 16)
        gemm_tile(query, Wqe, bqe, S + OFF_QF, Ed, 1, y * 32, blockIdx.x * 64);
    else
        gemm_tile(key_,  Wke, bke, S + OFF_KF, Ed, 1, (y - 16) * 32, blockIdx.x * 64);
}

// Launch 2: 4 projections + int8 weight quantization. grid (4, 32, 5)
__global__ void proj_trans_kernel(const float* __restrict__ W0,
                                  const float* __restrict__ Wv1,
                                  const float* __restrict__ W1,
                                  const float* __restrict__ W2)
{
    float* S = g_scratch;
    const int z = blockIdx.z;
    if (z < 4) {
        const float* A; const float* W; float* C;
        switch (z) {
            case 0: A = S + OFF_QF; W = W0;            C = S + OFF_QP; break;
            case 1: A = S + OFF_KF; W = W0 + Hd * Hd;  C = S + OFF_KP; break;
            case 2: A = S + OFF_QF; W = Wv1;           C = S + OFF_QV; break;
            default:A = S + OFF_KF; W = Wv1 + Hd * Hd; C = S + OFF_KV; break;
        }
        int M = (z == 1 || z == 3) ? 1024 : 512;
        if (blockIdx.y * 32 >= M) return;
        gemm_tile(A, W, nullptr, C, Hd, 0, blockIdx.y * 32, blockIdx.x * 64);
    } else {
        // int8 2-digit quantization of W1t/W2t rows. 64 blocks x 8 rows (warp/row).
        int lin = blockIdx.y * 4 + blockIdx.x;      // 0..127
        if (lin >= 64) return;
        int tid = threadIdx.x;
        int grow = lin * 8 + (tid >> 5);            // 0..511
        int layer = grow >> 8;
        int n = grow & 255;
        int lane = tid & 31;
        const float* W = layer ? W2 : W1;           // [k][n] row-major
        int k0 = lane * 8;
        float v[8];
        float m = 0.f;
        #pragma unroll
        for (int i = 0; i < 8; i++) {
            v[i] = __ldg(W + (size_t)(k0 + i) * 256 + n);
            m = fmaxf(m, fabsf(v[i]));
        }
        #pragma unroll
        for (int s = 16; s >= 1; s >>= 1)
            m = fmaxf(m, __shfl_xor_sync(0xffffffffu, m, s));
        float inv = m > 0.f ? 127.f / m : 0.f;
        int b1i[8], b2i[8];
        #pragma unroll
        for (int i = 0; i < 8; i++) {
            float t = v[i] * inv;
            b1i[i] = __float2int_rn(t);
            b2i[i] = __float2int_rn((t - (float)b1i[i]) * 254.f);
        }
        signed char* base1 = g_wq + (size_t)layer * 131072 + (size_t)n * 256 + k0;
        signed char* base2 = base1 + 65536;
        *(uint2*)base1 = make_uint2(
            (uint32_t)pack4(b1i[0], b1i[1], b1i[2], b1i[3]),
            (uint32_t)pack4(b1i[4], b1i[5], b1i[6], b1i[7]));
        *(uint2*)base2 = make_uint2(
            (uint32_t)pack4(b2i[0], b2i[1], b2i[2], b2i[3]),
            (uint32_t)pack4(b2i[4], b2i[5], b2i[6], b2i[7]));
        if (lane == 0) g_wscale[layer * 256 + n] = m * (1.f / 127.f);
    }
}

// ---------------------------------------------------------------------------
// int8 Ozaki fused pair kernel. CTA = (b, q, 64 k-pairs). M=64, N=256, K=256.
// 8 warps: 2 (M, 32 rows) x 4 (N, 64 cols). S1 = A1B1, S2 = A1B2 + A2B1.
// ---------------------------------------------------------------------------
#define AP8 272                          // bytes per A row (256 + 16 pad)
#define SM_A1 0
#define SM_A2 (64 * AP8)                 // 17408
#define SM_W  (2 * 64 * AP8)             // 34816
#define WCH   12288                      // one W chunk buf: 256 n x 48 B
#define SM_RMAX (SM_W + 4 * WCH)         // 83968 (4 x 64 floats; reused as partials)
#define SM_SA   (SM_RMAX + 1024)         // 84992 (64 floats)
#define SMEM_TOTAL (SM_SA + 256)         // 85248

__global__ void __launch_bounds__(256, 1)
pair_i8_kernel(const float* __restrict__ b0, const float* __restrict__ b1,
               const float* __restrict__ b2,
               const float* __restrict__ Wf, const float* __restrict__ bf,
               const float* __restrict__ bv1, const float* __restrict__ Wv2,
               const float* __restrict__ bv2,
               float* __restrict__ out)
{
    extern __shared__ char smem[];
    const uint32_t sbase = smem_to_u32(smem);
    float* rmax_sm = (float*)(smem + SM_RMAX);
    float* sA_sm   = (float*)(smem + SM_SA);

    const int tid = threadIdx.x;
    const int w   = tid >> 5;
    const int wm  = w >> 2;            // 0..1 : M group (32 rows)
    const int wn  = w & 3;             // 0..3 : N group (64 cols)
    const int lt  = tid & 31;
    const int lrow = lt >> 2;          // 0..7
    const int lc2  = (lt & 3) * 2;     // 0,2,4,6

    // ldmatrix lane offsets (16B granules)
    const uint32_t a_rowoff = (uint32_t)(wm * 32 + (lt & 15)) * AP8
                            + (uint32_t)((lt >> 4) & 1) * 16;
    const uint32_t b_rowoff = (uint32_t)(wn * 64 + (lt & 7) + ((lt >> 4) & 1) * 8) * 48
                            + (uint32_t)((lt >> 3) & 1) * 16;

    const int kb = blockIdx.x, q = blockIdx.y, b = blockIdx.z;
    const int qrow  = b * SQd + q;
    const int krow0 = b * SKd + kb * 64;

    const float* qp = g_scratch + OFF_QP + (size_t)qrow  * Hd;
    const float* kp = g_scratch + OFF_KP + (size_t)krow0 * Hd;
    const float* qv = g_scratch + OFF_QV + (size_t)qrow  * Hd;
    const float* kv = g_scratch + OFF_KV + (size_t)krow0 * Hd;

    // ---- prefetch W chunk 0 (layer 0, kc 0), both digits
    {
        #pragma unroll
        for (int d = 0; d < 2; d++)
            #pragma unroll
            for (int it = 0; it < 2; it++) {
                int u = tid + it * 256;          // 0..511
                int n = u >> 1, j = u & 1;
                const signed char* src = g_wq + d * 65536 + n * 256 + j * 16;
                cp16(sbase + SM_W + d * WCH + n * 48 + j * 16, src);
            }
        CP_COMMIT();
    }

    // ---- variance branch: v = relu(qv+kv+bv1); softplus(v.Wv2 + bv2)
    {
        const int r = tid >> 2, part = tid & 3;  // 64 rows x 4 threads
        const float* qvr = qv + part * 64;
        const float* kvr = kv + (size_t)r * Hd + part * 64;
        const float* bvr = bv1 + part * 64;
        const float* wvr = Wv2 + part * 64;
        float s = 0.f;
        #pragma unroll
        for (int i = 0; i < 16; i++) {
            float4 a = ldg4(qvr + i * 4);
            float4 c = ldg4(kvr + i * 4);
            float4 bb = ldg4(bvr + i * 4);
            float4 ww = ldg4(wvr + i * 4);
            s = fmaf(frelu(a.x + c.x + bb.x), ww.x, s);
            s = fmaf(frelu(a.y + c.y + bb.y), ww.y, s);
            s = fmaf(frelu(a.z + c.z + bb.z), ww.z, s);
            s = fmaf(frelu(a.w + c.w + bb.w), ww.w, s);
        }
        s += __shfl_xor_sync(0xffffffffu, s, 1);
        s += __shfl_xor_sync(0xffffffffu, s, 2);
        if (part == 0) {
            float x = s + __ldg(bv2);
            out[(size_t)Bsz * SQd * SKd + (size_t)qrow * SKd + kb * 64 + r] =
                fmaxf(x, 0.f) + log1pf(expf(-fabsf(x)));
        }
    }

    // ---- build A = relu(qp + kp + b0), rowmax, int8 2-digit quantize -> SMEM
    {
        const int row = tid >> 2, part = tid & 3;   // 4 threads per row, 64 elems each
        const int c0 = part * 64;
        const float* qpr = qp + c0;
        const float* kpr = kp + (size_t)row * Hd + c0;
        const float* b0r = b0 + c0;
        float a[64];
        float m = 0.f;
        #pragma unroll
        for (int j4 = 0; j4 < 16; j4++) {
            float4 aa = ldg4(qpr + j4 * 4);
            float4 cc = ldg4(kpr + j4 * 4);
            float4 bb = ldg4(b0r + j4 * 4);
            a[j4*4+0] = frelu(aa.x + cc.x + bb.x);
            a[j4*4+1] = frelu(aa.y + cc.y + bb.y);
            a[j4*4+2] = frelu(aa.z + cc.z + bb.z);
            a[j4*4+3] = frelu(aa.w + cc.w + bb.w);
            m = fmaxf(m, fmaxf(fmaxf(a[j4*4], a[j4*4+1]), fmaxf(a[j4*4+2], a[j4*4+3])));
        }
        m = fmaxf(m, __shfl_xor_sync(0xffffffffu, m, 1));
        m = fmaxf(m, __shfl_xor_sync(0xffffffffu, m, 2));
        float inv = m > 0.f ? 127.f / m : 0.f;
        if (part == 0) sA_sm[row] = m * (1.f / 127.f);
        #pragma unroll
        for (int j4 = 0; j4 < 16; j4++) {
            int q1[4], q2[4];
            #pragma unroll
            for (int e = 0; e < 4; e++) {
                float t = a[j4*4+e] * inv;
                q1[e] = __float2int_rn(t);
                q2[e] = __float2int_rn((t - (float)q1[e]) * 254.f);
            }
            uint32_t off = (uint32_t)row * AP8 + c0 + j4 * 4;
            *(int*)(smem + SM_A1 + off) = pack4(q1[0], q1[1], q1[2], q1[3]);
            *(int*)(smem + SM_A2 + off) = pack4(q2[0], q2[1], q2[2], q2[3]);
        }
    }
    CP_WAIT0();
    __syncthreads();

    // ---- accumulators: S1 (main), S2 (combined corrections), s32
    int S1[2][8][4], S2[2][8][4];
    #pragma unroll
    for (int mi = 0; mi < 2; mi++)
        #pragma unroll
        for (int ni = 0; ni < 8; ni++)
            #pragma unroll
            for (int jj = 0; jj < 4; jj++) { S1[mi][ni][jj] = 0; S2[mi][ni][jj] = 0; }

    const int r0g = wm * 32 + 0 * 16 + lrow;   // row pieces (mi, lrow/+8)

    // ---- 16 chunks of K=32: layer = g>>3, kc = g&7; double-buffered
    #pragma unroll 1
    for (int g = 0; g < 16; g++) {
        const int kc = g & 7;
        const uint32_t wb1 = sbase + SM_W + (uint32_t)(g & 1) * (2 * WCH);
        const uint32_t wb2 = wb1 + WCH;

        // prefetch next chunk (both digits)
        if (g + 1 < 16) {
            const signed char* Wl = g_wq + (size_t)((g + 1) >> 3) * 131072;
            const int nkc = (g + 1) & 7;
            const uint32_t dbase = sbase + SM_W + ((g + 1) & 1) * (2 * WCH);
            #pragma unroll
            for (int d = 0; d < 2; d++)
                #pragma unroll
                for (int it = 0; it < 2; it++) {
                    int u = tid + it * 256;
                    int n = u >> 1, j = u & 1;
                    cp16(dbase + d * WCH + n * 48 + j * 16,
                         Wl + d * 65536 + n * 256 + nkc * 32 + j * 16);
                }
            CP_COMMIT();
        }

        // ---- compute: 3 int8 mmas per tile
        {
            const uint32_t a_k = (uint32_t)kc * 32;
            uint32_t a1f[2][4], a2f[2][4], b1f[8][2], b2f[8][2];
            #pragma unroll
            for (int mi = 0; mi < 2; mi++)
                ldsm4(a1f[mi], sbase + SM_A1 + a_rowoff + (uint32_t)mi * 16 * AP8 + a_k);
            #pragma unroll
            for (int np = 0; np < 4; np++) {
                uint32_t r[4];
                ldsm4(r, wb1 + b_rowoff + (uint32_t)np * 16 * 48);
                b1f[2*np][0] = r[0]; b1f[2*np][1] = r[1];
                b1f[2*np+1][0] = r[2]; b1f[2*np+1][1] = r[3];
            }
            #pragma unroll
            for (int mi = 0; mi < 2; mi++)
                #pragma unroll
                for (int ni = 0; ni < 8; ni++)
                    mma_s8(S1[mi][ni], a1f[mi], b1f[ni]);
            #pragma unroll
            for (int np = 0; np < 4; np++) {
                uint32_t r[4];
                ldsm4(r, wb2 + b_rowoff + (uint32_t)np * 16 * 48);
                b2f[2*np][0] = r[0]; b2f[2*np][1] = r[1];
                b2f[2*np+1][0] = r[2]; b2f[2*np+1][1] = r[3];
            }
            #pragma unroll
            for (int mi = 0; mi < 2; mi++)
                #pragma unroll
                for (int ni = 0; ni < 8; ni++)
                    mma_s8(S2[mi][ni], a1f[mi], b2f[ni]);
            #pragma unroll
            for (int mi = 0; mi < 2; mi++)
                ldsm4(a2f[mi], sbase + SM_A2 + a_rowoff + (uint32_t)mi * 16 * AP8 + a_k);
            #pragma unroll
            for (int mi = 0; mi < 2; mi++)
                #pragma unroll
                for (int ni = 0; ni < 8; ni++)
                    mma_s8(S2[mi][ni], a2f[mi], b1f[ni]);
        }

        CP_WAIT0();
        __syncthreads();

        // ---- layer boundary: h1 = relu(D + b1) -> requantize -> A SMEM
        if (g == 7) {
            float sAo[2][2];
            #pragma unroll
            for (int mi = 0; mi < 2; mi++) {
                sAo[mi][0] = sA_sm[wm * 32 + mi * 16 + lrow];
                sAo[mi][1] = sA_sm[wm * 32 + mi * 16 + lrow + 8];
            }
            // pass 1: row maxes
            float mx[2][2] = {{0.f, 0.f}, {0.f, 0.f}};
            #pragma unroll
            for (int ni = 0; ni < 8; ni++) {
                int n = wn * 64 + ni * 8 + lc2;
                float2 sB = *(const float2*)(g_wscale + n);
                float2 bb = *(const float2*)(b1 + n);
                #pragma unroll
                for (int mi = 0; mi < 2; mi++) {
                    float t0 = (float)S1[mi][ni][0] + (float)S2[mi][ni][0] * INV254;
                    float t1 = (float)S1[mi][ni][1] + (float)S2[mi][ni][1] * INV254;
                    float t2 = (float)S1[mi][ni][2] + (float)S2[mi][ni][2] * INV254;
                    float t3 = (float)S1[mi][ni][3] + (float)S2[mi][ni][3] * INV254;
                    float v0 = frelu(fmaf(sAo[mi][0] * sB.x, t0, bb.x));
                    float v1 = frelu(fmaf(sAo[mi][0] * sB.y, t1, bb.y));
                    float v2 = frelu(fmaf(sAo[mi][1] * sB.x, t2, bb.x));
                    float v3 = frelu(fmaf(sAo[mi][1] * sB.y, t3, bb.y));
                    mx[mi][0] = fmaxf(mx[mi][0], fmaxf(v0, v1));
                    mx[mi][1] = fmaxf(mx[mi][1], fmaxf(v2, v3));
                }
            }
            #pragma unroll
            for (int mi = 0; mi < 2; mi++)
                #pragma unroll
                for (int hh = 0; hh < 2; hh++) {
                    float m = mx[mi][hh];
                    m = fmaxf(m, __shfl_xor_sync(0xffffffffu, m, 1));
                    m = fmaxf(m, __shfl_xor_sync(0xffffffffu, m, 2));
                    mx[mi][hh] = m;
                }
            if ((lt & 3) == 0) {
                #pragma unroll
                for (int mi = 0; mi < 2; mi++) {
                    rmax_sm[wn * 64 + wm * 32 + mi * 16 + lrow]     = mx[mi][0];
                    rmax_sm[wn * 64 + wm * 32 + mi * 16 + lrow + 8] = mx[mi][1];
                }
            }
            __syncthreads();
            if (tid < 64) {
                float m = fmaxf(fmaxf(rmax_sm[tid], rmax_sm[64 + tid]),
                                fmaxf(rmax_sm[128 + tid], rmax_sm[192 + tid]));
                sA_sm[tid] = m * (1.f / 127.f);
            }
            __syncthreads();
            float invr[2][2];
            #pragma unroll
            for (int mi = 0; mi < 2; mi++) {
                float s0 = sA_sm[wm * 32 + mi * 16 + lrow];
                float s1 = sA_sm[wm * 32 + mi * 16 + lrow + 8];
                invr[mi][0] = s0 > 0.f ? 1.f / s0 : 0.f;
                invr[mi][1] = s1 > 0.f ? 1.f / s1 : 0.f;
            }
            // pass 2: recompute, quantize, store
            #pragma unroll
            for (int ni = 0; ni < 8; ni++) {
                int n = wn * 64 + ni * 8 + lc2;
                float2 sB = *(const float2*)(g_wscale + n);
                float2 bb = *(const float2*)(b1 + n);
                #pragma unroll
                for (int mi = 0; mi < 2; mi++) {
                    #pragma unroll
                    for (int hh = 0; hh < 2; hh++) {
                        float t0 = (float)S1[mi][ni][hh*2]   + (float)S2[mi][ni][hh*2]   * INV254;
                        float t1 = (float)S1[mi][ni][hh*2+1] + (float)S2[mi][ni][hh*2+1] * INV254;
                        float v0 = frelu(fmaf(sAo[mi][hh] * sB.x, t0, bb.x));
                        float v1 = frelu(fmaf(sAo[mi][hh] * sB.y, t1, bb.y));
                        float u0 = v0 * invr[mi][hh];
                        float u1 = v1 * invr[mi][hh];
                        int q10 = __float2int_rn(u0);
                        int q11 = __float2int_rn(u1);
                        int q20 = __float2int_rn((u0 - (float)q10) * 254.f);
                        int q21 = __float2int_rn((u1 - (float)q11) * 254.f);
                        int row = wm * 32 + mi * 16 + lrow + hh * 8;
                        uint32_t off = (uint32_t)row * AP8 + n;
                        *(uint16_t*)(smem + SM_A1 + off) =
                            (uint16_t)((q10 & 0xff) | ((q11 & 0xff) << 8));
                        *(uint16_t*)(smem + SM_A2 + off) =
                            (uint16_t)((q20 & 0xff) | ((q21 & 0xff) << 8));
                        S1[mi][ni][hh*2] = 0;   S1[mi][ni][hh*2+1] = 0;
                        S2[mi][ni][hh*2] = 0;   S2[mi][ni][hh*2+1] = 0;
                    }
                }
            }
            __syncthreads();
        }
    }

    // ---- final epilogue: logit = relu(D + b2) . Wf + bf
    float sAn[2][2];
    #pragma unroll
    for (int mi = 0; mi < 2; mi++) {
        sAn[mi][0] = sA_sm[wm * 32 + mi * 16 + lrow];
        sAn[mi][1] = sA_sm[wm * 32 + mi * 16 + lrow + 8];
    }
    float ps[2][2] = {{0.f, 0.f}, {0.f, 0.f}};
    #pragma unroll
    for (int ni = 0; ni < 8; ni++) {
        int n = wn * 64 + ni * 8 + lc2;
        float2 sB = *(const float2*)(g_wscale + 256 + n);
        float2 bb = *(const float2*)(b2 + n);
        float2 wf = *(const float2*)(Wf + n);
        #pragma unroll
        for (int mi = 0; mi < 2; mi++) {
            float t0 = (float)S1[mi][ni][0] + (float)S2[mi][ni][0] * INV254;
            float t1 = (float)S1[mi][ni][1] + (float)S2[mi][ni][1] * INV254;
            float t2 = (float)S1[mi][ni][2] + (float)S2[mi][ni][2] * INV254;
            float t3 = (float)S1[mi][ni][3] + (float)S2[mi][ni][3] * INV254;
            ps[mi][0] = fmaf(frelu(fmaf(sAn[mi][0] * sB.x, t0, bb.x)), wf.x, ps[mi][0]);
            ps[mi][0] = fmaf(frelu(fmaf(sAn[mi][0] * sB.y, t1, bb.y)), wf.y, ps[mi][0]);
            ps[mi][1] = fmaf(frelu(fmaf(sAn[mi][1] * sB.x, t2, bb.x)), wf.x, ps[mi][1]);
            ps[mi][1] = fmaf(frelu(fmaf(sAn[mi][1] * sB.y, t3, bb.y)), wf.y, ps[mi][1]);
        }
    }
    #pragma unroll
    for (int mi = 0; mi < 2; mi++)
        #pragma unroll
        for (int hh = 0; hh < 2; hh++) {
            float s = ps[mi][hh];
            s += __shfl_xor_sync(0xffffffffu, s, 1);
            s += __shfl_xor_sync(0xffffffffu, s, 2);
            ps[mi][hh] = s;
        }
    if ((lt & 3) == 0) {
        #pragma unroll
        for (int mi = 0; mi < 2; mi++) {
            rmax_sm[wn * 64 + wm * 32 + mi * 16 + lrow]     = ps[mi][0];
            rmax_sm[wn * 64 + wm * 32 + mi * 16 + lrow + 8] = ps[mi][1];
        }
    }
    __syncthreads();
    if (tid < 64) {
        float s = rmax_sm[tid] + rmax_sm[64 + tid] + rmax_sm[128 + tid]
                + rmax_sm[192 + tid] + __ldg(bf);
        out[(size_t)qrow * SKd + kb * 64 + tid] = s;
    }
}

// ---------------------------------------------------------------------------
// Launch (3 launches per call)
// ---------------------------------------------------------------------------
extern "C" void kernel_launch(void* const* d_in, const int* in_sizes, int n_in,
                              void* d_out, int out_size)
{
    (void)in_sizes; (void)n_in; (void)out_size;
    const float* query = (const float*)d_in[0];
    const float* key_  = (const float*)d_in[1];
    const float* Wqe   = (const float*)d_in[2];
    const float* bqe   = (const float*)d_in[3];
    const float* Wke   = (const float*)d_in[4];
    const float* bke   = (const float*)d_in[5];
    const float* W0    = (const float*)d_in[6];
    const float* b0    = (const float*)d_in[7];
    const float* W1    = (const float*)d_in[8];
    const float* b1    = (const float*)d_in[9];
    const float* W2    = (const float*)d_in[10];
    const float* b2    = (const float*)d_in[11];
    const float* Wf    = (const float*)d_in[12];
    const float* bf    = (const float*)d_in[13];
    const float* Wv1   = (const float*)d_in[14];
    const float* bv1   = (const float*)d_in[15];
    const float* Wv2   = (const float*)d_in[16];
    const float* bv2   = (const float*)d_in[17];
    float* out = (float*)d_out;

    cudaFuncSetAttribute(pair_i8_kernel,
                         cudaFuncAttributeMaxDynamicSharedMemorySize, SMEM_TOTAL);

    // 1: encoders (qf, kf)
    encoder_kernel<<<dim3(4, 48), 256>>>(query, key_, Wqe, bqe, Wke, bke);
    // 2: projections + int8 weight quantization
    proj_trans_kernel<<<dim3(4, 32, 5), 256>>>(W0, Wv1, W1, W2);
    // 3: fused int8 pair MLP
    pair_i8_kernel<<<dim3(SKd / 64, SQd, Bsz), 256, SMEM_TOTAL>>>(
        b0, b1, b2, Wf, bf, bv1, Wv2, bv2, out);
}

// round 8
// speedup vs baseline: 2.8782x; 2.8782x over previous
#include <cuda_runtime.h>
#include <cuda_fp16.h>
#include <math.h>
#include <cstdint>

// Problem constants
#define Bsz 2
#define SQd 256
#define SKd 512
#define Ed  512
#define Hd  256

#define NQ (Bsz*SQd)   // 512
#define NK (Bsz*SKd)   // 1024
#define OFF_QF 0
#define OFF_KF (OFF_QF + NQ*Hd)
#define OFF_QP (OFF_KF + NK*Hd)
#define OFF_KP (OFF_QP + NQ*Hd)
#define OFF_QV (OFF_KP + NK*Hd)
#define OFF_KV (OFF_QV + NQ*Hd)
#define SCRATCH_FLOATS (OFF_KV + NK*Hd)

__device__ float g_scratch[SCRATCH_FLOATS];
// Transposed fp16 weights: [W1h][W2h], each [256 n][256 k]
__device__ __align__(16) __half g_wt[2 * 256 * 256];

__device__ __forceinline__ float frelu(float x) { return x > 0.f ? x : 0.f; }
__device__ __forceinline__ float4 ldg4(const float* p) { return __ldg((const float4*)p); }

__device__ __forceinline__ uint32_t smem_to_u32(const void* p) {
    uint32_t a;
    asm("{ .reg .u64 t; cvta.to.shared.u64 t, %1; cvt.u32.u64 %0, t; }" : "=r"(a) : "l"(p));
    return a;
}
__device__ __forceinline__ void cp16(uint32_t dst, const void* src) {
    asm volatile("cp.async.cg.shared.global [%0], [%1], 16;" :: "r"(dst), "l"(src));
}
#define CP_COMMIT() asm volatile("cp.async.commit_group;" ::: "memory")
#define CP_WAIT0()  asm volatile("cp.async.wait_group 0;" ::: "memory")

// fp16 inputs, fp32 accumulate
__device__ __forceinline__ void mma_f32acc(float* c, const uint32_t* a, const uint32_t* b) {
    asm volatile(
        "mma.sync.aligned.m16n8k16.row.col.f32.f16.f16.f32 "
        "{%0,%1,%2,%3}, {%4,%5,%6,%7}, {%8,%9}, {%0,%1,%2,%3};"
        : "+f"(c[0]), "+f"(c[1]), "+f"(c[2]), "+f"(c[3])
        : "r"(a[0]), "r"(a[1]), "r"(a[2]), "r"(a[3]), "r"(b[0]), "r"(b[1]));
}
__device__ __forceinline__ void ldsm4(uint32_t* r, uint32_t addr) {
    asm volatile("ldmatrix.sync.aligned.m8n8.x4.shared.b16 {%0,%1,%2,%3}, [%4];"
                 : "=r"(r[0]), "=r"(r[1]), "=r"(r[2]), "=r"(r[3]) : "r"(addr));
}

// fp16 hi/lo split of two fp32 values, packed
__device__ __forceinline__ void split2h(float x0, float x1, uint32_t& h, uint32_t& l) {
    __half h0 = __float2half_rn(x0), h1 = __float2half_rn(x1);
    float r0 = x0 - __half2float(h0), r1 = x1 - __half2float(h1);
    __half l0 = __float2half_rn(r0), l1 = __float2half_rn(r1);
    h = (uint32_t)__half_as_ushort(h0) | ((uint32_t)__half_as_ushort(h1) << 16);
    l = (uint32_t)__half_as_ushort(l0) | ((uint32_t)__half_as_ushort(l1) << 16);
}

// ---------------------------------------------------------------------------
// Prep GEMM tile (verified since R2)
// ---------------------------------------------------------------------------
__device__ void gemm_tile(const float* __restrict__ A,
                          const float* __restrict__ W,
                          const float* __restrict__ bias,
                          float* __restrict__ C,
                          int K, int act, int row0, int col0)
{
    __shared__ float As[32 * 32];
    __shared__ float Ws[32 * 64];
    const int tid = threadIdx.x;
    const int tr  = tid >> 4;
    const int tc  = tid & 15;

    float acc0x=0.f,acc0y=0.f,acc0z=0.f,acc0w=0.f,acc1x=0.f,acc1y=0.f,acc1z=0.f,acc1w=0.f;
    if (bias) {
        float4 bb = ldg4(bias + col0 + tc * 4);
        acc0x=bb.x;acc0y=bb.y;acc0z=bb.z;acc0w=bb.w;
        acc1x=bb.x;acc1y=bb.y;acc1z=bb.z;acc1w=bb.w;
    }
    for (int kc = 0; kc < K; kc += 32) {
        __syncthreads();
        {   int r = tid >> 3; int ck = (tid & 7) * 4;
            *(float4*)(As + r * 32 + ck) = ldg4(A + (size_t)(row0 + r) * K + kc + ck); }
        {
            #pragma unroll
            for (int i = 0; i < 2; i++) {
                int f = tid + 256 * i; int k = f >> 4; int c = (f & 15) * 4;
                *(float4*)(Ws + k * 64 + c) = ldg4(W + (size_t)(kc + k) * 256 + col0 + c);
            } }
        __syncthreads();
        #pragma unroll 8
        for (int k = 0; k < 32; k++) {
            float a0 = As[(tr * 2) * 32 + k];
            float a1 = As[(tr * 2 + 1) * 32 + k];
            float4 w = *(float4*)(Ws + k * 64 + tc * 4);
            acc0x = fmaf(a0, w.x, acc0x); acc0y = fmaf(a0, w.y, acc0y);
            acc0z = fmaf(a0, w.z, acc0z); acc0w = fmaf(a0, w.w, acc0w);
            acc1x = fmaf(a1, w.x, acc1x); acc1y = fmaf(a1, w.y, acc1y);
            acc1z = fmaf(a1, w.z, acc1z); acc1w = fmaf(a1, w.w, acc1w);
        }
    }
    if (act) {
        acc0x=frelu(acc0x);acc0y=frelu(acc0y);acc0z=frelu(acc0z);acc0w=frelu(acc0w);
        acc1x=frelu(acc1x);acc1y=frelu(acc1y);acc1z=frelu(acc1z);acc1w=frelu(acc1w);
    }
    *(float4*)(C + (size_t)(row0+tr*2)  *256 + col0 + tc*4) = make_float4(acc0x,acc0y,acc0z,acc0w);
    *(float4*)(C + (size_t)(row0+tr*2+1)*256 + col0 + tc*4) = make_float4(acc1x,acc1y,acc1z,acc1w);
}

// Launch 1: both encoders. grid (4, 48)
__global__ void encoder_kernel(const float* __restrict__ query,
                               const float* __restrict__ key_,
                               const float* __restrict__ Wqe, const float* __restrict__ bqe,
                               const float* __restrict__ Wke, const float* __restrict__ bke)
{
    float* S = g_scratch;
    int y = blockIdx.y;
    if (y < 16)
        gemm_tile(query, Wqe, bqe, S + OFF_QF, Ed, 1, y * 32, blockIdx.x * 64);
    else
        gemm_tile(key_,  Wke, bke, S + OFF_KF, Ed, 1, (y - 16) * 32, blockIdx.x * 64);
}

// Launch 2: 4 projections + weight transpose (fp16). grid (4, 32, 5)
__global__ void proj_trans_kernel(const float* __restrict__ W0,
                                  const float* __restrict__ Wv1,
                                  const float* __restrict__ W1,
                                  const float* __restrict__ W2)
{
    float* S = g_scratch;
    const int z = blockIdx.z;
    if (z < 4) {
        const float* A; const float* W; float* C;
        switch (z) {
            case 0: A = S + OFF_QF; W = W0;            C = S + OFF_QP; break;
            case 1: A = S + OFF_KF; W = W0 + Hd * Hd;  C = S + OFF_KP; break;
            case 2: A = S + OFF_QF; W = Wv1;           C = S + OFF_QV; break;
            default:A = S + OFF_KF; W = Wv1 + Hd * Hd; C = S + OFF_KV; break;
        }
        int M = (z == 1 || z == 3) ? 1024 : 512;
        if (blockIdx.y * 32 >= M) return;
        gemm_tile(A, W, nullptr, C, Hd, 0, blockIdx.y * 32, blockIdx.x * 64);
    } else {
        // transpose + fp16 round of W1, W2 into g_wt (Wt[n][k] row-major)
        int lin = blockIdx.y * 4 + blockIdx.x;      // 0..127
        const float* W = (lin >= 64) ? W2 : W1;
        __half* oh = g_wt + (size_t)(lin >= 64 ? 1 : 0) * 65536;
        int base = (lin & 63) * 1024;
        #pragma unroll
        for (int t = 0; t < 4; t++) {
            int e = base + t * 256 + threadIdx.x;
            int n = e >> 8, k = e & 255;
            oh[e] = __float2half_rn(__ldg(W + (size_t)k * 256 + n));
        }
    }
}

// ---------------------------------------------------------------------------
// HMMA fused pair kernel. CTA = (b, q, 128 k-pairs). M=128, N=256, K=256.
// 8 warps: 2 (M) x 4 (N). A fp16 hi/lo split vs fp16 W: D = (Ah + Al) @ Wh.
// Both terms accumulate into the same fp32 accumulator.
// ---------------------------------------------------------------------------
#define APITCH 264                       // fp16 elems per A row (528 B)
#define SM_AH 0
#define SM_AL (128 * APITCH * 2)         // 67584
#define SM_W  (2 * 128 * APITCH * 2)     // 135168
#define WBUF_BYTES (256 * 40 * 2)        // 20480, pitch 80 B
#define SM_PART (SM_W + 2 * WBUF_BYTES)  // 176128
#define SMEM_TOTAL (SM_PART + 512 * 4)   // 178176

__global__ void __launch_bounds__(256, 1)
pair_mma_kernel(const float* __restrict__ b0, const float* __restrict__ b1,
                const float* __restrict__ b2,
                const float* __restrict__ Wf, const float* __restrict__ bf,
                const float* __restrict__ bv1, const float* __restrict__ Wv2,
                const float* __restrict__ bv2,
                float* __restrict__ out)
{
    extern __shared__ char smem[];
    const uint32_t sbase = smem_to_u32(smem);

    const int tid = threadIdx.x;
    const int w   = tid >> 5;
    const int wm  = w >> 2;            // 0..1 : M group (64 rows)
    const int wn  = w & 3;             // 0..3 : N group (64 cols)
    const int lt  = tid & 31;
    const int lrow = lt >> 2;          // 0..7
    const int lc2  = (lt & 3) * 2;     // 0,2,4,6

    // ldmatrix per-lane row offsets
    const uint32_t a_rowoff = (uint32_t)(wm * 64 + (lt & 15)) * (APITCH * 2)
                            + (uint32_t)((lt >> 4) * 8) * 2;
    const uint32_t b_rowoff = (uint32_t)(wn * 64 + (lt & 7) + ((lt >> 4) & 1) * 8) * 80
                            + (uint32_t)((lt >> 3) & 1) * 16;

    const int kb = blockIdx.x, q = blockIdx.y, b = blockIdx.z;
    const int qrow  = b * SQd + q;
    const int krow0 = b * SKd + kb * 128;

    const float* qp = g_scratch + OFF_QP + (size_t)qrow  * Hd;
    const float* kp = g_scratch + OFF_KP + (size_t)krow0 * Hd;
    const float* qv = g_scratch + OFF_QV + (size_t)qrow  * Hd;
    const float* kv = g_scratch + OFF_KV + (size_t)krow0 * Hd;

    // ---- prefetch W chunk 0 (layer 0) via cp.async
    {
        #pragma unroll
        for (int it = 0; it < 4; it++) {
            int u = tid + it * 256;             // 0..1023
            int n = u >> 2, j = u & 3;
            cp16(sbase + SM_W + n * 80 + j * 16, g_wt + n * 256 + j * 8);
        }
        CP_COMMIT();
    }

    // ---- variance branch: v = relu(qv+kv+bv1); softplus(v.Wv2 + bv2)
    {
        const int r = tid >> 1, part = tid & 1;
        const float* qvr = qv + part * 128;
        const float* kvr = kv + (size_t)r * Hd + part * 128;
        const float* bvr = bv1 + part * 128;
        const float* wvr = Wv2 + part * 128;
        float s = 0.f;
        #pragma unroll
        for (int i = 0; i < 32; i++) {
            float4 a = ldg4(qvr + i * 4);
            float4 c = ldg4(kvr + i * 4);
            float4 bb = ldg4(bvr + i * 4);
            float4 ww = ldg4(wvr + i * 4);
            s = fmaf(frelu(a.x + c.x + bb.x), ww.x, s);
            s = fmaf(frelu(a.y + c.y + bb.y), ww.y, s);
            s = fmaf(frelu(a.z + c.z + bb.z), ww.z, s);
            s = fmaf(frelu(a.w + c.w + bb.w), ww.w, s);
        }
        s += __shfl_down_sync(0xffffffffu, s, 1);
        if (part == 0) {
            float x = s + __ldg(bv2);
            out[(size_t)Bsz * SQd * SKd + (size_t)qrow * SKd + kb * 128 + r] =
                fmaxf(x, 0.f) + log1pf(expf(-fabsf(x)));
        }
    }

    // ---- build A = relu(qp + kp + b0), fp16 hi/lo split -> SMEM
    {
        const int row = tid >> 1, half = (tid & 1) * 128;
        const float* qpr = qp + half;
        const float* kpr = kp + (size_t)row * Hd + half;
        const float* b0r = b0 + half;
        #pragma unroll
        for (int j4 = 0; j4 < 32; j4++) {
            float4 a  = ldg4(qpr + j4 * 4);
            float4 c  = ldg4(kpr + j4 * 4);
            float4 bb = ldg4(b0r + j4 * 4);
            float x0 = frelu(a.x + c.x + bb.x);
            float x1 = frelu(a.y + c.y + bb.y);
            float x2 = frelu(a.z + c.z + bb.z);
            float x3 = frelu(a.w + c.w + bb.w);
            uint32_t h0, l0, h1, l1;
            split2h(x0, x1, h0, l0);
            split2h(x2, x3, h1, l1);
            uint32_t off = (uint32_t)row * (APITCH * 2) + (half + j4 * 4) * 2;
            *(uint2*)(smem + SM_AH + off) = make_uint2(h0, h1);
            *(uint2*)(smem + SM_AL + off) = make_uint2(l0, l1);
        }
    }
    CP_WAIT0();
    __syncthreads();

    // ---- accumulators: fp32 c[4][8][4]
    float c[4][8][4];
    #pragma unroll
    for (int mi = 0; mi < 4; mi++)
        #pragma unroll
        for (int ni = 0; ni < 8; ni++)
            #pragma unroll
            for (int jj = 0; jj < 4; jj++) c[mi][ni][jj] = 0.f;

    // ---- 16 chunks of K=32: layer = g>>3, kc = g&7; double-buffered cp.async
    #pragma unroll 1
    for (int g = 0; g < 16; g++) {
        const int kc = g & 7;
        const uint32_t wbufH = sbase + SM_W + (uint32_t)(g & 1) * WBUF_BYTES;

        // prefetch next chunk
        if (g + 1 < 16) {
            const __half* Wh = g_wt + (size_t)((g + 1) >> 3) * 65536;
            const int nkc = (g + 1) & 7;
            const uint32_t dbase = sbase + SM_W + ((g + 1) & 1) * WBUF_BYTES;
            #pragma unroll
            for (int it = 0; it < 4; it++) {
                int u = tid + it * 256;
                int n = u >> 2, j = u & 3;
                cp16(dbase + n * 80 + j * 16, Wh + n * 256 + nkc * 32 + j * 8);
            }
            CP_COMMIT();
        }

        // compute on current chunk: 2 k16 steps
        #pragma unroll
        for (int ks = 0; ks < 2; ks++) {
            const uint32_t a_k = (uint32_t)(kc * 32 + ks * 16) * 2;
            const uint32_t b_k = (uint32_t)ks * 32;

            uint32_t afh[4][4], afl[4][4], bh[8][2];
            #pragma unroll
            for (int mi = 0; mi < 4; mi++)
                ldsm4(afh[mi], sbase + SM_AH + a_rowoff + (uint32_t)mi * 16 * (APITCH * 2) + a_k);
            #pragma unroll
            for (int np = 0; np < 4; np++) {
                uint32_t r[4];
                ldsm4(r, wbufH + b_rowoff + (uint32_t)np * 16 * 80 + b_k);
                bh[2*np][0] = r[0]; bh[2*np][1] = r[1];
                bh[2*np+1][0] = r[2]; bh[2*np+1][1] = r[3];
            }
            // Ah @ Wh
            #pragma unroll
            for (int mi = 0; mi < 4; mi++)
                #pragma unroll
                for (int ni = 0; ni < 8; ni++)
                    mma_f32acc(c[mi][ni], afh[mi], bh[ni]);
            #pragma unroll
            for (int mi = 0; mi < 4; mi++)
                ldsm4(afl[mi], sbase + SM_AL + a_rowoff + (uint32_t)mi * 16 * (APITCH * 2) + a_k);
            // Al @ Wh (same accumulator)
            #pragma unroll
            for (int mi = 0; mi < 4; mi++)
                #pragma unroll
                for (int ni = 0; ni < 8; ni++)
                    mma_f32acc(c[mi][ni], afl[mi], bh[ni]);
        }

        CP_WAIT0();
        __syncthreads();

        // ---- between layers: h1 = relu(D + b1) -> split -> A SMEM; reset accum
        if (g == 7) {
            #pragma unroll
            for (int ni = 0; ni < 8; ni++) {
                int n = wn * 64 + ni * 8 + lc2;
                float2 bb = *(const float2*)(b1 + n);
                #pragma unroll
                for (int mi = 0; mi < 4; mi++) {
                    int m1 = wm * 64 + mi * 16 + lrow;
                    float x0 = frelu(c[mi][ni][0] + bb.x);
                    float x1 = frelu(c[mi][ni][1] + bb.y);
                    float y0 = frelu(c[mi][ni][2] + bb.x);
                    float y1 = frelu(c[mi][ni][3] + bb.y);
                    uint32_t h, l;
                    uint32_t off1 = (uint32_t)m1 * (APITCH * 2) + n * 2;
                    split2h(x0, x1, h, l);
                    *(uint32_t*)(smem + SM_AH + off1) = h;
                    *(uint32_t*)(smem + SM_AL + off1) = l;
                    uint32_t off2 = off1 + 8 * (APITCH * 2);
                    split2h(y0, y1, h, l);
                    *(uint32_t*)(smem + SM_AH + off2) = h;
                    *(uint32_t*)(smem + SM_AL + off2) = l;
                    c[mi][ni][0] = 0.f; c[mi][ni][1] = 0.f;
                    c[mi][ni][2] = 0.f; c[mi][ni][3] = 0.f;
                }
            }
            __syncthreads();
        }
    }

    // ---- final epilogue: logit = relu(D + b2) . Wf + bf
    float* part = (float*)(smem + SM_PART);
    float ps1[4], ps2[4];
    #pragma unroll
    for (int mi = 0; mi < 4; mi++) { ps1[mi] = 0.f; ps2[mi] = 0.f; }
    #pragma unroll
    for (int ni = 0; ni < 8; ni++) {
        int n = wn * 64 + ni * 8 + lc2;
        float2 bb = *(const float2*)(b2 + n);
        float2 wf = *(const float2*)(Wf + n);
        #pragma unroll
        for (int mi = 0; mi < 4; mi++) {
            ps1[mi] = fmaf(frelu(c[mi][ni][0] + bb.x), wf.x, ps1[mi]);
            ps1[mi] = fmaf(frelu(c[mi][ni][1] + bb.y), wf.y, ps1[mi]);
            ps2[mi] = fmaf(frelu(c[mi][ni][2] + bb.x), wf.x, ps2[mi]);
            ps2[mi] = fmaf(frelu(c[mi][ni][3] + bb.y), wf.y, ps2[mi]);
        }
    }
    #pragma unroll
    for (int mi = 0; mi < 4; mi++) {
        ps1[mi] += __shfl_xor_sync(0xffffffffu, ps1[mi], 1);
        ps1[mi] += __shfl_xor_sync(0xffffffffu, ps1[mi], 2);
        ps2[mi] += __shfl_xor_sync(0xffffffffu, ps2[mi], 1);
        ps2[mi] += __shfl_xor_sync(0xffffffffu, ps2[mi], 2);
    }
    if ((lt & 3) == 0) {
        #pragma unroll
        for (int mi = 0; mi < 4; mi++) {
            int m1 = wm * 64 + mi * 16 + lrow;
            part[wn * 128 + m1]     = ps1[mi];
            part[wn * 128 + m1 + 8] = ps2[mi];
        }
    }
    __syncthreads();
    if (tid < 128) {
        float s = part[tid] + part[128 + tid] + part[256 + tid] + part[384 + tid]
                + __ldg(bf);
        out[(size_t)qrow * SKd + kb * 128 + tid] = s;
    }
}

// ---------------------------------------------------------------------------
// Launch (3 launches per call)
// ---------------------------------------------------------------------------
extern "C" void kernel_launch(void* const* d_in, const int* in_sizes, int n_in,
                              void* d_out, int out_size)
{
    (void)in_sizes; (void)n_in; (void)out_size;
    const float* query = (const float*)d_in[0];
    const float* key_  = (const float*)d_in[1];
    const float* Wqe   = (const float*)d_in[2];
    const float* bqe   = (const float*)d_in[3];
    const float* Wke   = (const float*)d_in[4];
    const float* bke   = (const float*)d_in[5];
    const float* W0    = (const float*)d_in[6];
    const float* b0    = (const float*)d_in[7];
    const float* W1    = (const float*)d_in[8];
    const float* b1    = (const float*)d_in[9];
    const float* W2    = (const float*)d_in[10];
    const float* b2    = (const float*)d_in[11];
    const float* Wf    = (const float*)d_in[12];
    const float* bf    = (const float*)d_in[13];
    const float* Wv1   = (const float*)d_in[14];
    const float* bv1   = (const float*)d_in[15];
    const float* Wv2   = (const float*)d_in[16];
    const float* bv2   = (const float*)d_in[17];
    float* out = (float*)d_out;

    cudaFuncSetAttribute(pair_mma_kernel,
                         cudaFuncAttributeMaxDynamicSharedMemorySize, SMEM_TOTAL);

    // 1: encoders (qf, kf)
    encoder_kernel<<<dim3(4, 48), 256>>>(query, key_, Wqe, bqe, Wke, bke);
    // 2: projections (qp,kp,qv,kv) + W1/W2 transpose (fp16)
    proj_trans_kernel<<<dim3(4, 32, 5), 256>>>(W0, Wv1, W1, W2);
    // 3: fused HMMA pair MLP (2-term split)
    pair_mma_kernel<<<dim3(SKd / 128, SQd, Bsz), 256, SMEM_TOTAL>>>(
        b0, b1, b2, Wf, bf, bv1, Wv2, bv2, out);
}